// round 12
// baseline (speedup 1.0000x reference)
#include <cuda_runtime.h>
#include <cuda_bf16.h>

#define NF 39
#define NV 200000
#define NB 16384
#define RPB 32              // rows per CTA
#define NT 256              // 8 warps
#define GRID (NB / RPB)     // 512
#define GROUPS 10           // 4 fields per group, K=64

// B (weights) pre-transposed: plane(hi/lo) x n(64) x k(640, zero-padded), bf16
static __device__ __align__(16) __nv_bfloat16 g_wg[2 * 64 * 640];

__global__ void __launch_bounds__(256)
prep_wg(const float* __restrict__ W1, const float* __restrict__ Wi)
{
    int i = blockIdx.x * blockDim.x + threadIdx.x;
    if (i >= 64 * 640) return;
    int n = i / 640, k = i - n * 640;
    float val = 0.0f;
    if (k < 624) {
        int f = k >> 4, e = k & 15;
        val = (n < 32) ? W1[n * 624 + f * 16 + e] : Wi[(n - 32) * 624 + f * 16 + e];
    }
    __nv_bfloat16 hi = __float2bfloat16(val);
    __nv_bfloat16 lo = __float2bfloat16(val - __bfloat162float(hi));
    g_wg[i] = hi;
    g_wg[64 * 640 + i] = lo;
}

static __device__ __forceinline__ void mma_bf16(float* c, const unsigned* a,
                                                unsigned b0, unsigned b1) {
    asm("mma.sync.aligned.m16n8k16.row.col.f32.bf16.bf16.f32 "
        "{%0,%1,%2,%3}, {%4,%5,%6,%7}, {%8,%9}, {%0,%1,%2,%3};"
        : "+f"(c[0]), "+f"(c[1]), "+f"(c[2]), "+f"(c[3])
        : "r"(a[0]), "r"(a[1]), "r"(a[2]), "r"(a[3]), "r"(b0), "r"(b1));
}

// ---------- smem layout (bytes) ----------
#define A_HI 0              // 32 rows x 36 words  = 4608
#define A_LO 4608
#define B_HI 9216           // 64 n x 36 words     = 9216
#define B_LO 18432
#define OFF_MLP 27648       // 2176 floats = 8704
#define SMEM_TOT 36352
// epilogue aliases:
#define OFF_XD A_HI         // 32 x 66 floats = 8448 (A_HI+A_LO = 9216)
#define OFF_XB B_HI         // 32 x 33 floats = 4224
#define OFF_YB B_LO

extern __shared__ unsigned char smem_raw[];

__global__ void __launch_bounds__(NT, 4)
pnn_mma(const int* __restrict__ Xi, const float* __restrict__ Xv,
        const float* __restrict__ tables,
        const float* __restrict__ l1w, const float* __restrict__ l1b,
        const float* __restrict__ l2w, const float* __restrict__ l2b,
        const float* __restrict__ lw, const float* __restrict__ lb,
        float* __restrict__ out)
{
    const int tid = threadIdx.x;
    const int w = tid >> 5, l = tid & 31;
    const int qr = l >> 2, ql = l & 3;
    const int mt = w & 1;           // m-tile (rows 16mt..16mt+15)
    const int nh = w >> 1;          // n-quarter (n-blocks 2nh, 2nh+1)
    const int row0 = blockIdx.x * RPB;

    float* mlp = reinterpret_cast<float*>(smem_raw + OFF_MLP);
    const unsigned* Ah = reinterpret_cast<const unsigned*>(smem_raw + A_HI);
    const unsigned* Al = reinterpret_cast<const unsigned*>(smem_raw + A_LO);
    const unsigned* Bh = reinterpret_cast<const unsigned*>(smem_raw + B_HI);
    const unsigned* Bl = reinterpret_cast<const unsigned*>(smem_raw + B_LO);

    // ---- stage MLP weights ----
    for (int i = tid; i < 1024; i += NT) { mlp[i] = l1w[i]; mlp[1024 + i] = l2w[i]; }
    if (tid < 32) {
        mlp[2048 + tid] = l1b[tid];
        mlp[2080 + tid] = l2b[tid];
        mlp[2112 + tid] = lw[tid];
        if (tid == 0) mlp[2144] = lb[0];
    }

    // gather unit: tid -> (row, field-lane, half): 32 x 4 x 2 = 256
    const int grow = tid >> 3, gfl = (tid >> 1) & 3, ghalf = tid & 1;
    // B stage unit: tid -> (plane, n, half)
    const int bplane = tid >> 7, bn = (tid >> 1) & 63, bhalf = tid & 1;

    float4 aq[2]; float av;
    uint4 bu[4];

    // ---- prefetch group 0 ----
    {
        int f = gfl;
        int idx = Xi[(row0 + grow) * NF + f];
        av = Xv[(row0 + grow) * NF + f];
        const float4* s = reinterpret_cast<const float4*>(
            tables + ((long)f * NV + idx) * 16) + ghalf * 2;
        aq[0] = s[0]; aq[1] = s[1];
        const uint4* bs = reinterpret_cast<const uint4*>(
            reinterpret_cast<const unsigned char*>(g_wg) +
            (long)bplane * 81920 + bn * 1280 + bhalf * 64);
        bu[0] = bs[0]; bu[1] = bs[1]; bu[2] = bs[2]; bu[3] = bs[3];
    }

    float acc[2][4];
#pragma unroll
    for (int nb = 0; nb < 2; nb++)
#pragma unroll
        for (int j = 0; j < 4; j++) acc[nb][j] = 0.0f;

    // ---- stage group 0 ----
    {
        // A: split + scale 8 floats
        float x[8];
        x[0] = aq[0].x * av; x[1] = aq[0].y * av; x[2] = aq[0].z * av; x[3] = aq[0].w * av;
        x[4] = aq[1].x * av; x[5] = aq[1].y * av; x[6] = aq[1].z * av; x[7] = aq[1].w * av;
        unsigned hw[4], lw2[4];
#pragma unroll
        for (int j = 0; j < 4; j++) {
            __nv_bfloat162 h2 = __floats2bfloat162_rn(x[2*j], x[2*j+1]);
            float ra = x[2*j]   - __bfloat162float(h2.x);
            float rb = x[2*j+1] - __bfloat162float(h2.y);
            __nv_bfloat162 l2 = __floats2bfloat162_rn(ra, rb);
            hw[j]  = *reinterpret_cast<unsigned*>(&h2);
            lw2[j] = *reinterpret_cast<unsigned*>(&l2);
        }
        unsigned boff = (grow * 36 + gfl * 8 + ghalf * 4) * 4;
        *reinterpret_cast<uint4*>(smem_raw + A_HI + boff) = make_uint4(hw[0], hw[1], hw[2], hw[3]);
        *reinterpret_cast<uint4*>(smem_raw + A_LO + boff) = make_uint4(lw2[0], lw2[1], lw2[2], lw2[3]);
        // B
        unsigned char* dst = smem_raw + (bplane ? B_LO : B_HI) + bn * 144 + bhalf * 64;
        *reinterpret_cast<uint4*>(dst)      = bu[0];
        *reinterpret_cast<uint4*>(dst + 16) = bu[1];
        *reinterpret_cast<uint4*>(dst + 32) = bu[2];
        *reinterpret_cast<uint4*>(dst + 48) = bu[3];
    }
    __syncthreads();

    for (int g = 0; g < GROUPS; g++) {
        const bool pf = (g + 1 < GROUPS);

        // ---- prefetch group g+1 (LDG issued before compute) ----
        if (pf) {
            int f = (g + 1) * 4 + gfl;
            if (f < NF) {
                int idx = Xi[(row0 + grow) * NF + f];
                av = Xv[(row0 + grow) * NF + f];
                const float4* s = reinterpret_cast<const float4*>(
                    tables + ((long)f * NV + idx) * 16) + ghalf * 2;
                aq[0] = s[0]; aq[1] = s[1];
            } else {
                av = 0.0f;
                aq[0] = aq[1] = make_float4(0.f, 0.f, 0.f, 0.f);
            }
            const uint4* bs = reinterpret_cast<const uint4*>(
                reinterpret_cast<const unsigned char*>(g_wg) +
                (long)bplane * 81920 + bn * 1280 + (g + 1) * 128 + bhalf * 64);
            bu[0] = bs[0]; bu[1] = bs[1]; bu[2] = bs[2]; bu[3] = bs[3];
        }

        // ---- compute: 4 k-steps x 2 n-blocks x 3 passes ----
        {
            const int abase = (mt * 16 + qr) * 36 + ql;
#pragma unroll
            for (int ks = 0; ks < 4; ks++) {
                const int ao = abase + ks * 8;
                unsigned ahi[4], alo[4];
                ahi[0] = Ah[ao];       ahi[1] = Ah[ao + 288];
                ahi[2] = Ah[ao + 4];   ahi[3] = Ah[ao + 292];
                alo[0] = Al[ao];       alo[1] = Al[ao + 288];
                alo[2] = Al[ao + 4];   alo[3] = Al[ao + 292];
#pragma unroll
                for (int i = 0; i < 2; i++) {
                    const int nb = nh * 2 + i;
                    const int bo = (nb * 8 + qr) * 36 + ks * 8 + ql;
                    unsigned bh0 = Bh[bo], bh1 = Bh[bo + 4];
                    unsigned bl0 = Bl[bo], bl1 = Bl[bo + 4];
                    mma_bf16(acc[i], ahi, bh0, bh1);
                    mma_bf16(acc[i], alo, bh0, bh1);
                    mma_bf16(acc[i], ahi, bl0, bl1);
                }
            }
        }
        __syncthreads();

        // ---- stage group g+1 ----
        if (pf) {
            float x[8];
            x[0] = aq[0].x * av; x[1] = aq[0].y * av; x[2] = aq[0].z * av; x[3] = aq[0].w * av;
            x[4] = aq[1].x * av; x[5] = aq[1].y * av; x[6] = aq[1].z * av; x[7] = aq[1].w * av;
            unsigned hw[4], lw2[4];
#pragma unroll
            for (int j = 0; j < 4; j++) {
                __nv_bfloat162 h2 = __floats2bfloat162_rn(x[2*j], x[2*j+1]);
                float ra = x[2*j]   - __bfloat162float(h2.x);
                float rb = x[2*j+1] - __bfloat162float(h2.y);
                __nv_bfloat162 l2 = __floats2bfloat162_rn(ra, rb);
                hw[j]  = *reinterpret_cast<unsigned*>(&h2);
                lw2[j] = *reinterpret_cast<unsigned*>(&l2);
            }
            unsigned boff = (grow * 36 + gfl * 8 + ghalf * 4) * 4;
            *reinterpret_cast<uint4*>(smem_raw + A_HI + boff) = make_uint4(hw[0], hw[1], hw[2], hw[3]);
            *reinterpret_cast<uint4*>(smem_raw + A_LO + boff) = make_uint4(lw2[0], lw2[1], lw2[2], lw2[3]);
            unsigned char* dst = smem_raw + (bplane ? B_LO : B_HI) + bn * 144 + bhalf * 64;
            *reinterpret_cast<uint4*>(dst)      = bu[0];
            *reinterpret_cast<uint4*>(dst + 16) = bu[1];
            *reinterpret_cast<uint4*>(dst + 32) = bu[2];
            *reinterpret_cast<uint4*>(dst + 48) = bu[3];
            __syncthreads();
        }
    }
    __syncthreads();   // compute done; safe to alias A/B regions

    // ---- dump D to xd[32][66] ----
    float* xd = reinterpret_cast<float*>(smem_raw + OFF_XD);
    {
        const int rA = mt * 16 + qr, rB = rA + 8;
#pragma unroll
        for (int i = 0; i < 2; i++) {
            int c = (nh * 2 + i) * 8 + 2 * ql;
            *reinterpret_cast<float2*>(xd + rA * 66 + c) = make_float2(acc[i][0], acc[i][1]);
            *reinterpret_cast<float2*>(xd + rB * 66 + c) = make_float2(acc[i][2], acc[i][3]);
        }
    }
    __syncthreads();

    // ---- x = fo + s^2 ----
    float* xb = reinterpret_cast<float*>(smem_raw + OFF_XB);
    float* yb = reinterpret_cast<float*>(smem_raw + OFF_YB);
    {
        const int rr = tid >> 3, q = tid & 7;
#pragma unroll
        for (int j = 0; j < 4; j++) {
            int d = q * 4 + j;
            float fo = xd[rr * 66 + d];
            float sv = xd[rr * 66 + 32 + d];
            xb[rr * 33 + d] = fmaf(sv, sv, fo);
        }
    }
    __syncthreads();

    // ---- MLP: 8 threads/row, 4 outputs each ----
    const int rr = tid >> 3, q = tid & 7;
    {
        const float* xr = xb + rr * 33;
#pragma unroll
        for (int j = 0; j < 4; j++) {
            int jj = q * 4 + j;
            float s = mlp[2048 + jj];
            const float* wrow = mlp + jj * 32;
#pragma unroll
            for (int k = 0; k < 32; k++) s = fmaf(xr[k], wrow[k], s);
            yb[rr * 33 + jj] = fmaxf(s, 0.0f);
        }
    }
    __syncthreads();
    {
        const float* yr = yb + rr * 33;
#pragma unroll
        for (int j = 0; j < 4; j++) {
            int jj = q * 4 + j;
            float s = mlp[2080 + jj];
            const float* wrow = mlp + 1024 + jj * 32;
#pragma unroll
            for (int k = 0; k < 32; k++) s = fmaf(yr[k], wrow[k], s);
            xb[rr * 33 + jj] = fmaxf(s, 0.0f);
        }
    }
    __syncthreads();
    if (q == 0) {
        float s = mlp[2144];
        const float* zr = xb + rr * 33;
#pragma unroll
        for (int k = 0; k < 32; k++) s = fmaf(zr[k], mlp[2112 + k], s);
        out[row0 + rr] = s;
    }
}

extern "C" void kernel_launch(void* const* d_in, const int* in_sizes, int n_in,
                              void* d_out, int out_size)
{
    const int*   Xi     = (const int*)  d_in[0];
    const float* Xv     = (const float*)d_in[1];
    const float* tables = (const float*)d_in[2];
    const float* W1     = (const float*)d_in[3];
    const float* Wi     = (const float*)d_in[4];
    const float* l1w    = (const float*)d_in[5];
    const float* l1b    = (const float*)d_in[6];
    const float* l2w    = (const float*)d_in[7];
    const float* l2b    = (const float*)d_in[8];
    const float* lw     = (const float*)d_in[9];
    const float* lb     = (const float*)d_in[10];

    prep_wg<<<(64 * 640 + 255) / 256, 256>>>(W1, Wi);

    cudaFuncSetAttribute(pnn_mma, cudaFuncAttributeMaxDynamicSharedMemorySize, SMEM_TOT);
    pnn_mma<<<GRID, NT, SMEM_TOT>>>(
        Xi, Xv, tables, l1w, l1b, l2w, l2b, lw, lb, (float*)d_out);
}

// round 14
// speedup vs baseline: 1.1003x; 1.1003x over previous
#include <cuda_runtime.h>
#include <cuda_bf16.h>

#define NF 39
#define NV 200000
#define NB 16384
#define RPB 64              // rows per CTA
#define NT 512              // 16 warps
#define GRID (NB / RPB)     // 256
#define GROUPS 10           // 4 fields per group, K=64

// B (weights) pre-transposed: plane(hi/lo) x n(64) x k(640, zero-padded), bf16
static __device__ __align__(16) __nv_bfloat16 g_wg[2 * 64 * 640];

__global__ void __launch_bounds__(256)
prep_wg(const float* __restrict__ W1, const float* __restrict__ Wi)
{
    int i = blockIdx.x * blockDim.x + threadIdx.x;
    if (i >= 64 * 640) return;
    int n = i / 640, k = i - n * 640;
    float val = 0.0f;
    if (k < 624) {
        int f = k >> 4, e = k & 15;
        val = (n < 32) ? W1[n * 624 + f * 16 + e] : Wi[(n - 32) * 624 + f * 16 + e];
    }
    __nv_bfloat16 hi = __float2bfloat16(val);
    __nv_bfloat16 lo = __float2bfloat16(val - __bfloat162float(hi));
    g_wg[i] = hi;
    g_wg[64 * 640 + i] = lo;
}

static __device__ __forceinline__ void mma_bf16(float* c, const unsigned* a,
                                                unsigned b0, unsigned b1) {
    asm("mma.sync.aligned.m16n8k16.row.col.f32.bf16.bf16.f32 "
        "{%0,%1,%2,%3}, {%4,%5,%6,%7}, {%8,%9}, {%0,%1,%2,%3};"
        : "+f"(c[0]), "+f"(c[1]), "+f"(c[2]), "+f"(c[3])
        : "r"(a[0]), "r"(a[1]), "r"(a[2]), "r"(a[3]), "r"(b0), "r"(b1));
}

// ---------- smem layout (bytes) ----------
#define A_HI 0              // 64 rows x 36 words = 9216
#define A_LO 9216
#define B_HI 18432          // 64 n x 36 words    = 9216
#define B_LO 27648
#define OFF_MLP 36864       // 2176 floats = 8704
#define SMEM_TOT 45568
// epilogue aliases:
#define OFF_XD A_HI         // 64 x 66 floats = 16896 <= 18432
#define OFF_XB B_HI         // 64 x 33 floats = 8448
#define OFF_YB B_LO

extern __shared__ unsigned char smem_raw[];

__global__ void __launch_bounds__(NT, 2)
pnn_mma(const int* __restrict__ Xi, const float* __restrict__ Xv,
        const float* __restrict__ tables,
        const float* __restrict__ l1w, const float* __restrict__ l1b,
        const float* __restrict__ l2w, const float* __restrict__ l2b,
        const float* __restrict__ lw, const float* __restrict__ lb,
        float* __restrict__ out)
{
    const int tid = threadIdx.x;
    const int w = tid >> 5, l = tid & 31;
    const int qr = l >> 2, ql = l & 3;
    const int mt = w & 3;           // m-tile: rows 16mt..16mt+15
    const int nq = w >> 2;          // n-quarter: n-blocks 2nq, 2nq+1
    const int row0 = blockIdx.x * RPB;

    float* mlp = reinterpret_cast<float*>(smem_raw + OFF_MLP);
    const unsigned* Ah = reinterpret_cast<const unsigned*>(smem_raw + A_HI);
    const unsigned* Al = reinterpret_cast<const unsigned*>(smem_raw + A_LO);
    const unsigned* Bh = reinterpret_cast<const unsigned*>(smem_raw + B_HI);
    const unsigned* Bl = reinterpret_cast<const unsigned*>(smem_raw + B_LO);

    // ---- stage MLP weights ----
    for (int i = tid; i < 1024; i += NT) { mlp[i] = l1w[i]; mlp[1024 + i] = l2w[i]; }
    if (tid < 32) {
        mlp[2048 + tid] = l1b[tid];
        mlp[2080 + tid] = l2b[tid];
        mlp[2112 + tid] = lw[tid];
        if (tid == 0) mlp[2144] = lb[0];
    }

    // gather unit: tid -> (row, field-lane, half): 64 x 4 x 2 = 512
    const int grow = tid >> 3, gfl = (tid >> 1) & 3, ghalf = tid & 1;
    // B stage unit: tid -> (plane, n, quarter): 2 x 64 x 4 = 512, 32B each
    const int bplane = tid >> 8, bn = (tid >> 2) & 63, bq = tid & 3;

    float4 aq[2]; float av;
    uint4 bu[2];

    // ---- prefetch group 0 ----
    {
        int f = gfl;
        int idx = Xi[(row0 + grow) * NF + f];
        av = Xv[(row0 + grow) * NF + f];
        const float4* s = reinterpret_cast<const float4*>(
            tables + ((long)f * NV + idx) * 16) + ghalf * 2;
        aq[0] = s[0]; aq[1] = s[1];
        const uint4* bs = reinterpret_cast<const uint4*>(
            reinterpret_cast<const unsigned char*>(g_wg) +
            (long)bplane * 81920 + bn * 1280 + bq * 32);
        bu[0] = bs[0]; bu[1] = bs[1];
    }

    float acc[2][4];
#pragma unroll
    for (int nb = 0; nb < 2; nb++)
#pragma unroll
        for (int j = 0; j < 4; j++) acc[nb][j] = 0.0f;

    // ---- stage group 0 ----
    {
        float x[8];
        x[0] = aq[0].x * av; x[1] = aq[0].y * av; x[2] = aq[0].z * av; x[3] = aq[0].w * av;
        x[4] = aq[1].x * av; x[5] = aq[1].y * av; x[6] = aq[1].z * av; x[7] = aq[1].w * av;
        unsigned hw[4], lw2[4];
#pragma unroll
        for (int j = 0; j < 4; j++) {
            __nv_bfloat162 h2 = __floats2bfloat162_rn(x[2*j], x[2*j+1]);
            float ra = x[2*j]   - __bfloat162float(h2.x);
            float rb = x[2*j+1] - __bfloat162float(h2.y);
            __nv_bfloat162 l2 = __floats2bfloat162_rn(ra, rb);
            hw[j]  = *reinterpret_cast<unsigned*>(&h2);
            lw2[j] = *reinterpret_cast<unsigned*>(&l2);
        }
        unsigned boff = (grow * 36 + gfl * 8 + ghalf * 4) * 4;
        *reinterpret_cast<uint4*>(smem_raw + A_HI + boff) = make_uint4(hw[0], hw[1], hw[2], hw[3]);
        *reinterpret_cast<uint4*>(smem_raw + A_LO + boff) = make_uint4(lw2[0], lw2[1], lw2[2], lw2[3]);
        unsigned char* dst = smem_raw + (bplane ? B_LO : B_HI) + bn * 144 + bq * 32;
        *reinterpret_cast<uint4*>(dst)      = bu[0];
        *reinterpret_cast<uint4*>(dst + 16) = bu[1];
    }
    __syncthreads();

    for (int g = 0; g < GROUPS; g++) {
        const bool pf = (g + 1 < GROUPS);

        // ---- prefetch group g+1 (LDG issued before compute) ----
        if (pf) {
            int f = (g + 1) * 4 + gfl;
            if (f < NF) {
                int idx = Xi[(row0 + grow) * NF + f];
                av = Xv[(row0 + grow) * NF + f];
                const float4* s = reinterpret_cast<const float4*>(
                    tables + ((long)f * NV + idx) * 16) + ghalf * 2;
                aq[0] = s[0]; aq[1] = s[1];
            } else {
                av = 0.0f;
                aq[0] = aq[1] = make_float4(0.f, 0.f, 0.f, 0.f);
            }
            const uint4* bs = reinterpret_cast<const uint4*>(
                reinterpret_cast<const unsigned char*>(g_wg) +
                (long)bplane * 81920 + bn * 1280 + (g + 1) * 128 + bq * 32);
            bu[0] = bs[0]; bu[1] = bs[1];
        }

        // ---- compute: 4 k-steps x 2 n-blocks x 3 passes ----
        {
            const int abase = (mt * 16 + qr) * 36 + ql;
#pragma unroll
            for (int ks = 0; ks < 4; ks++) {
                const int ao = abase + ks * 8;
                unsigned ahi[4], alo[4];
                ahi[0] = Ah[ao];       ahi[1] = Ah[ao + 288];
                ahi[2] = Ah[ao + 4];   ahi[3] = Ah[ao + 292];
                alo[0] = Al[ao];       alo[1] = Al[ao + 288];
                alo[2] = Al[ao + 4];   alo[3] = Al[ao + 292];
#pragma unroll
                for (int i = 0; i < 2; i++) {
                    const int nb = nq * 2 + i;
                    const int bo = (nb * 8 + qr) * 36 + ks * 8 + ql;
                    unsigned bh0 = Bh[bo], bh1 = Bh[bo + 4];
                    unsigned bl0 = Bl[bo], bl1 = Bl[bo + 4];
                    mma_bf16(acc[i], ahi, bh0, bh1);
                    mma_bf16(acc[i], alo, bh0, bh1);
                    mma_bf16(acc[i], ahi, bl0, bl1);
                }
            }
        }
        __syncthreads();

        // ---- stage group g+1 ----
        if (pf) {
            float x[8];
            x[0] = aq[0].x * av; x[1] = aq[0].y * av; x[2] = aq[0].z * av; x[3] = aq[0].w * av;
            x[4] = aq[1].x * av; x[5] = aq[1].y * av; x[6] = aq[1].z * av; x[7] = aq[1].w * av;
            unsigned hw[4], lw2[4];
#pragma unroll
            for (int j = 0; j < 4; j++) {
                __nv_bfloat162 h2 = __floats2bfloat162_rn(x[2*j], x[2*j+1]);
                float ra = x[2*j]   - __bfloat162float(h2.x);
                float rb = x[2*j+1] - __bfloat162float(h2.y);
                __nv_bfloat162 l2 = __floats2bfloat162_rn(ra, rb);
                hw[j]  = *reinterpret_cast<unsigned*>(&h2);
                lw2[j] = *reinterpret_cast<unsigned*>(&l2);
            }
            unsigned boff = (grow * 36 + gfl * 8 + ghalf * 4) * 4;
            *reinterpret_cast<uint4*>(smem_raw + A_HI + boff) = make_uint4(hw[0], hw[1], hw[2], hw[3]);
            *reinterpret_cast<uint4*>(smem_raw + A_LO + boff) = make_uint4(lw2[0], lw2[1], lw2[2], lw2[3]);
            unsigned char* dst = smem_raw + (bplane ? B_LO : B_HI) + bn * 144 + bq * 32;
            *reinterpret_cast<uint4*>(dst)      = bu[0];
            *reinterpret_cast<uint4*>(dst + 16) = bu[1];
            __syncthreads();
        }
    }
    __syncthreads();   // compute done; safe to alias A/B regions

    // ---- dump D to xd[64][66] ----
    float* xd = reinterpret_cast<float*>(smem_raw + OFF_XD);
    {
        const int rA = mt * 16 + qr, rB = rA + 8;
#pragma unroll
        for (int i = 0; i < 2; i++) {
            int c = (nq * 2 + i) * 8 + 2 * ql;
            *reinterpret_cast<float2*>(xd + rA * 66 + c) = make_float2(acc[i][0], acc[i][1]);
            *reinterpret_cast<float2*>(xd + rB * 66 + c) = make_float2(acc[i][2], acc[i][3]);
        }
    }
    __syncthreads();

    // ---- x = fo + s^2 ----
    float* xb = reinterpret_cast<float*>(smem_raw + OFF_XB);
    float* yb = reinterpret_cast<float*>(smem_raw + OFF_YB);
    const int rr = tid >> 3, q = tid & 7;
    {
#pragma unroll
        for (int j = 0; j < 4; j++) {
            int d = q * 4 + j;
            float fo = xd[rr * 66 + d];
            float sv = xd[rr * 66 + 32 + d];
            xb[rr * 33 + d] = fmaf(sv, sv, fo);
        }
    }
    __syncthreads();

    // ---- MLP: 8 threads/row, 4 outputs each ----
    {
        const float* xr = xb + rr * 33;
#pragma unroll
        for (int j = 0; j < 4; j++) {
            int jj = q * 4 + j;
            float s = mlp[2048 + jj];
            const float* wrow = mlp + jj * 32;
#pragma unroll
            for (int k = 0; k < 32; k++) s = fmaf(xr[k], wrow[k], s);
            yb[rr * 33 + jj] = fmaxf(s, 0.0f);
        }
    }
    __syncthreads();
    {
        const float* yr = yb + rr * 33;
#pragma unroll
        for (int j = 0; j < 4; j++) {
            int jj = q * 4 + j;
            float s = mlp[2080 + jj];
            const float* wrow = mlp + 1024 + jj * 32;
#pragma unroll
            for (int k = 0; k < 32; k++) s = fmaf(yr[k], wrow[k], s);
            xb[rr * 33 + jj] = fmaxf(s, 0.0f);
        }
    }
    __syncthreads();
    if (q == 0) {
        float s = mlp[2144];
        const float* zr = xb + rr * 33;
#pragma unroll
        for (int k = 0; k < 32; k++) s = fmaf(zr[k], mlp[2112 + k], s);
        out[row0 + rr] = s;
    }
}

extern "C" void kernel_launch(void* const* d_in, const int* in_sizes, int n_in,
                              void* d_out, int out_size)
{
    const int*   Xi     = (const int*)  d_in[0];
    const float* Xv     = (const float*)d_in[1];
    const float* tables = (const float*)d_in[2];
    const float* W1     = (const float*)d_in[3];
    const float* Wi     = (const float*)d_in[4];
    const float* l1w    = (const float*)d_in[5];
    const float* l1b    = (const float*)d_in[6];
    const float* l2w    = (const float*)d_in[7];
    const float* l2b    = (const float*)d_in[8];
    const float* lw     = (const float*)d_in[9];
    const float* lb     = (const float*)d_in[10];

    prep_wg<<<(64 * 640 + 255) / 256, 256>>>(W1, Wi);

    cudaFuncSetAttribute(pnn_mma, cudaFuncAttributeMaxDynamicSharedMemorySize, SMEM_TOT);
    pnn_mma<<<GRID, NT, SMEM_TOT>>>(
        Xi, Xv, tables, l1w, l1b, l2w, l2b, lw, lb, (float*)d_out);
}

// round 15
// speedup vs baseline: 1.3778x; 1.2522x over previous
#include <cuda_runtime.h>
#include <cuda_fp16.h>

#define NF 39
#define NV 200000
#define NB 16384
#define RPB 64              // rows per CTA
#define NT 128              // 4 warps
#define GRID (NB / RPB)     // 256
#define GROUPS 10           // 4 fields per group, K=64

// B weights fp16, single plane: [n=64][k=640 zero-padded]
static __device__ __align__(16) __half g_wh[64 * 640];

__global__ void __launch_bounds__(256)
prep_wh(const float* __restrict__ W1, const float* __restrict__ Wi)
{
    int i = blockIdx.x * blockDim.x + threadIdx.x;
    if (i >= 64 * 640) return;
    int n = i / 640, k = i - n * 640;
    float val = 0.0f;
    if (k < 624) {
        int f = k >> 4, e = k & 15;
        val = (n < 32) ? W1[n * 624 + f * 16 + e] : Wi[(n - 32) * 624 + f * 16 + e];
    }
    g_wh[i] = __float2half_rn(val);
}

static __device__ __forceinline__ void mma_f16(float* c, const unsigned* a,
                                               unsigned b0, unsigned b1) {
    asm("mma.sync.aligned.m16n8k16.row.col.f32.f16.f16.f32 "
        "{%0,%1,%2,%3}, {%4,%5,%6,%7}, {%8,%9}, {%0,%1,%2,%3};"
        : "+f"(c[0]), "+f"(c[1]), "+f"(c[2]), "+f"(c[3])
        : "r"(a[0]), "r"(a[1]), "r"(a[2]), "r"(a[3]), "r"(b0), "r"(b1));
}

// ---------- smem layout (bytes) ----------
// A planes double-buffered (stage s): padded 36 words (=144B) per row
#define A_HI(s) ((s) * 9216)            // 0, 9216
#define A_LO(s) (18432 + (s) * 9216)    // 18432, 27648
#define B_S(s)  (36864 + (s) * 9216)    // 36864, 46080
#define OFF_MLP 55296                   // 2176 floats = 8704
#define SMEM_TOT 64000
// epilogue aliases (after final sync):
#define OFF_XD 0                        // 64 x 66 floats = 16896
#define OFF_XB 36864                    // 64 x 33 floats = 8448
#define OFF_YB 45312                    // 8448

extern __shared__ unsigned char smem_raw[];

// split 16 scaled floats into fp16 hi (8 half2 words) + fp16 lo residual
static __device__ __forceinline__ void split16h(const float* x, unsigned* hi, unsigned* lo) {
#pragma unroll
    for (int j = 0; j < 8; j++) {
        __half ha = __float2half_rn(x[2 * j]);
        __half hb = __float2half_rn(x[2 * j + 1]);
        float ra = x[2 * j]     - __half2float(ha);
        float rb = x[2 * j + 1] - __half2float(hb);
        __half2 h2 = __halves2half2(ha, hb);
        __half2 l2 = __halves2half2(__float2half_rn(ra), __float2half_rn(rb));
        hi[j] = *reinterpret_cast<unsigned*>(&h2);
        lo[j] = *reinterpret_cast<unsigned*>(&l2);
    }
}

__global__ void __launch_bounds__(NT)
pnn_mma(const int* __restrict__ Xi, const float* __restrict__ Xv,
        const float* __restrict__ tables,
        const float* __restrict__ l1w, const float* __restrict__ l1b,
        const float* __restrict__ l2w, const float* __restrict__ l2b,
        const float* __restrict__ lw, const float* __restrict__ lb,
        float* __restrict__ out)
{
    const int tid = threadIdx.x;
    const int w = tid >> 5, l = tid & 31;
    const int qr = l >> 2, ql = l & 3;
    const int mt = w;               // warp = m-tile (rows 16w..16w+15), all 8 n-blocks
    const int row0 = blockIdx.x * RPB;

    float* mlp = reinterpret_cast<float*>(smem_raw + OFF_MLP);

    // ---- stage MLP weights ----
    for (int i = tid; i < 1024; i += NT) { mlp[i] = l1w[i]; mlp[1024 + i] = l2w[i]; }
    if (tid < 32) {
        mlp[2048 + tid] = l1b[tid];
        mlp[2080 + tid] = l2b[tid];
        mlp[2112 + tid] = lw[tid];
        if (tid == 0) mlp[2144] = lb[0];
    }

    // gather: thread handles 2 units; unit = (row = tid&63, field-in-group gf0 / gf0+2)
    const int grow = tid & 63;
    const int gf0 = tid >> 6;       // 0 or 1; second unit uses gf0+2
    // B stage: thread -> (n = tid>>1, half = tid&1), 64B each
    const int bn = tid >> 1, bh = tid & 1;

    // two in-flight A gather register sets + one B set
    float4 aqs[2][2][4];
    float  avs[2][2];
    uint4  bu[4];

    const float4* tab4 = reinterpret_cast<const float4*>(tables);

    auto issueA = [&](int g, int set) {
#pragma unroll
        for (int u = 0; u < 2; u++) {
            int f = g * 4 + gf0 + u * 2;
            if (f < NF) {
                int idx = Xi[(row0 + grow) * NF + f];
                avs[set][u] = Xv[(row0 + grow) * NF + f];
                const float4* s = tab4 + ((long)f * NV + idx) * 4;
                aqs[set][u][0] = s[0]; aqs[set][u][1] = s[1];
                aqs[set][u][2] = s[2]; aqs[set][u][3] = s[3];
            } else {
                avs[set][u] = 0.0f;
                aqs[set][u][0] = aqs[set][u][1] = aqs[set][u][2] = aqs[set][u][3] =
                    make_float4(0.f, 0.f, 0.f, 0.f);
            }
        }
    };
    auto issueB = [&](int g) {
        const uint4* bs = reinterpret_cast<const uint4*>(
            reinterpret_cast<const unsigned char*>(g_wh) + bn * 1280 + g * 128 + bh * 64);
        bu[0] = bs[0]; bu[1] = bs[1]; bu[2] = bs[2]; bu[3] = bs[3];
    };
    auto stageAB = [&](int g, int set) {
#pragma unroll
        for (int u = 0; u < 2; u++) {
            const int fl = gf0 + u * 2;
            const float v = avs[set][u];
            float x[16];
#pragma unroll
            for (int j = 0; j < 4; j++) {
                float4 q = aqs[set][u][j];
                x[4*j] = q.x * v; x[4*j+1] = q.y * v; x[4*j+2] = q.z * v; x[4*j+3] = q.w * v;
            }
            unsigned hi[8], lo[8];
            split16h(x, hi, lo);
            const unsigned boff = grow * 144 + fl * 32;
            *reinterpret_cast<uint4*>(smem_raw + A_HI(g & 1) + boff)      = make_uint4(hi[0], hi[1], hi[2], hi[3]);
            *reinterpret_cast<uint4*>(smem_raw + A_HI(g & 1) + boff + 16) = make_uint4(hi[4], hi[5], hi[6], hi[7]);
            *reinterpret_cast<uint4*>(smem_raw + A_LO(g & 1) + boff)      = make_uint4(lo[0], lo[1], lo[2], lo[3]);
            *reinterpret_cast<uint4*>(smem_raw + A_LO(g & 1) + boff + 16) = make_uint4(lo[4], lo[5], lo[6], lo[7]);
        }
        unsigned char* dst = smem_raw + B_S(g & 1) + bn * 144 + bh * 64;
        *reinterpret_cast<uint4*>(dst)      = bu[0];
        *reinterpret_cast<uint4*>(dst + 16) = bu[1];
        *reinterpret_cast<uint4*>(dst + 32) = bu[2];
        *reinterpret_cast<uint4*>(dst + 48) = bu[3];
    };

    float acc[8][4];
#pragma unroll
    for (int nb = 0; nb < 8; nb++)
#pragma unroll
        for (int j = 0; j < 4; j++) acc[nb][j] = 0.0f;

    // ---- prologue: groups 0 and 1 in flight ----
    issueA(0, 0);
    issueA(1, 1);
    issueB(0);
    stageAB(0, 0);
    __syncthreads();

    for (int g = 0; g < GROUPS; g++) {
        // depth-2 A prefetch + depth-1 B prefetch
        if (g + 2 < GROUPS) issueA(g + 2, g & 1);
        if (g + 1 < GROUPS) issueB(g + 1);

        // ---- compute group g: 4 k-steps x 8 n-blocks x 2 passes ----
        {
            const unsigned* Ah = reinterpret_cast<const unsigned*>(smem_raw + A_HI(g & 1));
            const unsigned* Al = reinterpret_cast<const unsigned*>(smem_raw + A_LO(g & 1));
            const unsigned* Bp = reinterpret_cast<const unsigned*>(smem_raw + B_S(g & 1));
            const int abase = (mt * 16 + qr) * 36 + ql;
#pragma unroll
            for (int ks = 0; ks < 4; ks++) {
                const int ao = abase + ks * 8;
                unsigned ahi[4], alo[4];
                ahi[0] = Ah[ao];     ahi[1] = Ah[ao + 288];
                ahi[2] = Ah[ao + 4]; ahi[3] = Ah[ao + 292];
                alo[0] = Al[ao];     alo[1] = Al[ao + 288];
                alo[2] = Al[ao + 4]; alo[3] = Al[ao + 292];
#pragma unroll
                for (int nb = 0; nb < 8; nb++) {
                    const int bo = (nb * 8 + qr) * 36 + ks * 8 + ql;
                    unsigned b0 = Bp[bo], b1 = Bp[bo + 4];
                    mma_f16(acc[nb], ahi, b0, b1);
                    mma_f16(acc[nb], alo, b0, b1);
                }
            }
        }

        // ---- stage group g+1 into the other buffer; one barrier per group ----
        if (g + 1 < GROUPS) {
            stageAB(g + 1, (g + 1) & 1);
            __syncthreads();
        }
    }
    __syncthreads();   // compute done; safe to alias A/B regions

    // ---- dump D to xd[64][66] ----
    float* xd = reinterpret_cast<float*>(smem_raw + OFF_XD);
    {
        const int rA = mt * 16 + qr, rB = rA + 8;
#pragma unroll
        for (int nb = 0; nb < 8; nb++) {
            int c = nb * 8 + 2 * ql;
            *reinterpret_cast<float2*>(xd + rA * 66 + c) = make_float2(acc[nb][0], acc[nb][1]);
            *reinterpret_cast<float2*>(xd + rB * 66 + c) = make_float2(acc[nb][2], acc[nb][3]);
        }
    }
    __syncthreads();

    // ---- x = fo + s^2 ; MLP (2 threads/row) ----
    float* xb = reinterpret_cast<float*>(smem_raw + OFF_XB);
    float* yb = reinterpret_cast<float*>(smem_raw + OFF_YB);
    const int rr = tid >> 1, hh = tid & 1;
    {
#pragma unroll
        for (int j = 0; j < 16; j++) {
            int d = hh * 16 + j;
            float fo = xd[rr * 66 + d];
            float sv = xd[rr * 66 + 32 + d];
            xb[rr * 33 + d] = fmaf(sv, sv, fo);
        }
    }
    __syncthreads();
    {
        const float* xr = xb + rr * 33;
#pragma unroll
        for (int j = 0; j < 16; j++) {
            int jj = hh * 16 + j;
            float s = mlp[2048 + jj];
            const float* wrow = mlp + jj * 32;
#pragma unroll
            for (int k = 0; k < 32; k++) s = fmaf(xr[k], wrow[k], s);
            yb[rr * 33 + jj] = fmaxf(s, 0.0f);
        }
    }
    __syncthreads();
    {
        const float* yr = yb + rr * 33;
#pragma unroll
        for (int j = 0; j < 16; j++) {
            int jj = hh * 16 + j;
            float s = mlp[2080 + jj];
            const float* wrow = mlp + 1024 + jj * 32;
#pragma unroll
            for (int k = 0; k < 32; k++) s = fmaf(yr[k], wrow[k], s);
            xb[rr * 33 + jj] = fmaxf(s, 0.0f);
        }
    }
    __syncthreads();
    if (hh == 0) {
        float s = mlp[2144];
        const float* zr = xb + rr * 33;
#pragma unroll
        for (int k = 0; k < 32; k++) s = fmaf(zr[k], mlp[2112 + k], s);
        out[row0 + rr] = s;
    }
}

extern "C" void kernel_launch(void* const* d_in, const int* in_sizes, int n_in,
                              void* d_out, int out_size)
{
    const int*   Xi     = (const int*)  d_in[0];
    const float* Xv     = (const float*)d_in[1];
    const float* tables = (const float*)d_in[2];
    const float* W1     = (const float*)d_in[3];
    const float* Wi     = (const float*)d_in[4];
    const float* l1w    = (const float*)d_in[5];
    const float* l1b    = (const float*)d_in[6];
    const float* l2w    = (const float*)d_in[7];
    const float* l2b    = (const float*)d_in[8];
    const float* lw     = (const float*)d_in[9];
    const float* lb     = (const float*)d_in[10];

    prep_wh<<<(64 * 640 + 255) / 256, 256>>>(W1, Wi);

    cudaFuncSetAttribute(pnn_mma, cudaFuncAttributeMaxDynamicSharedMemorySize, SMEM_TOT);
    pnn_mma<<<GRID, NT, SMEM_TOT>>>(
        Xi, Xv, tables, l1w, l1b, l2w, l2b, lw, lb, (float*)d_out);
}

// round 16
// speedup vs baseline: 1.5502x; 1.1252x over previous
#include <cuda_runtime.h>
#include <cuda_fp16.h>

#define NF 39
#define NV 200000
#define NB 16384
#define RPW 16              // rows per warp = per CTA
#define GRID (NB / RPW)     // 1024

// B fragments precomputed in mma lane order: [(f*8 + nb)*32 + lane] -> uint2 {b0,b1}
static __device__ __align__(16) uint2 g_bf[NF * 8 * 32];

__global__ void __launch_bounds__(256)
prep_bf(const float* __restrict__ W1, const float* __restrict__ Wi)
{
    int i = blockIdx.x * blockDim.x + threadIdx.x;
    if (i >= NF * 8 * 32) return;
    int l = i & 31, nb = (i >> 5) & 7, f = i >> 8;
    int qr = l >> 2, ql = l & 3;
    int n = nb * 8 + qr;
    const float* W = (n < 32) ? (W1 + n * 624) : (Wi + (n - 32) * 624);
    int k0 = f * 16 + 2 * ql;
    __half2 b0 = __floats2half2_rn(W[k0],     W[k0 + 1]);   // k = 2ql, 2ql+1   @ n
    __half2 b1 = __floats2half2_rn(W[k0 + 8], W[k0 + 9]);   // k = 2ql+8, 2ql+9 @ n
    uint2 v;
    v.x = *reinterpret_cast<unsigned*>(&b0);
    v.y = *reinterpret_cast<unsigned*>(&b1);
    g_bf[i] = v;
}

static __device__ __forceinline__ void mma_f16(float* c, const unsigned* a,
                                               unsigned b0, unsigned b1) {
    asm("mma.sync.aligned.m16n8k16.row.col.f32.f16.f16.f32 "
        "{%0,%1,%2,%3}, {%4,%5,%6,%7}, {%8,%9}, {%0,%1,%2,%3};"
        : "+f"(c[0]), "+f"(c[1]), "+f"(c[2]), "+f"(c[3])
        : "r"(a[0]), "r"(a[1]), "r"(a[2]), "r"(a[3]), "r"(b0), "r"(b1));
}

__global__ void __launch_bounds__(32)
pnn_mma(const int* __restrict__ Xi, const float* __restrict__ Xv,
        const float* __restrict__ tables,
        const float* __restrict__ l1w, const float* __restrict__ l1b,
        const float* __restrict__ l2w, const float* __restrict__ l2b,
        const float* __restrict__ lw, const float* __restrict__ lb,
        float* __restrict__ out)
{
    __shared__ int   Xis[RPW * NF];        // 624
    __shared__ float Xvs[RPW * NF];
    __shared__ float mlp[2176];
    __shared__ float xb[RPW * 33];
    __shared__ float yb[RPW * 33];

    const int l = threadIdx.x;
    const int qr = l >> 2, ql = l & 3;
    const int row0 = blockIdx.x * RPW;

    // ---- stage Xi/Xv (float4/int4) + MLP weights (float4) ----
    {
        const int4*   xs4 = reinterpret_cast<const int4*>(Xi + row0 * NF);
        const float4* xv4 = reinterpret_cast<const float4*>(Xv + row0 * NF);
        for (int i = l; i < 156; i += 32) {
            reinterpret_cast<int4*>(Xis)[i]   = xs4[i];
            reinterpret_cast<float4*>(Xvs)[i] = xv4[i];
        }
        const float4* w1 = reinterpret_cast<const float4*>(l1w);
        const float4* w2 = reinterpret_cast<const float4*>(l2w);
        for (int i = l; i < 256; i += 32) {
            reinterpret_cast<float4*>(mlp)[i]       = w1[i];
            reinterpret_cast<float4*>(mlp + 1024)[i] = w2[i];
        }
        mlp[2048 + l] = l1b[l];
        mlp[2080 + l] = l2b[l];
        mlp[2112 + l] = lw[l];
        if (l == 0) mlp[2144] = lb[0];
    }
    __syncwarp();

    const int rA = qr, rB = qr + 8;        // this lane's fragment rows

    float acc[8][4];
#pragma unroll
    for (int nb = 0; nb < 8; nb++)
#pragma unroll
        for (int j = 0; j < 4; j++) acc[nb][j] = 0.0f;

    // depth-2 register pipeline of raw A fragments
    float2 ta[2][4];
    float  tv[2][2];

    {   // field 0
        int ia = Xis[rA * NF], ib = Xis[rB * NF];
        tv[0][0] = Xvs[rA * NF]; tv[0][1] = Xvs[rB * NF];
        const float2* pa = reinterpret_cast<const float2*>(tables + ((long)ia) * 16);
        const float2* pb = reinterpret_cast<const float2*>(tables + ((long)ib) * 16);
        ta[0][0] = pa[ql]; ta[0][1] = pa[ql + 4];
        ta[0][2] = pb[ql]; ta[0][3] = pb[ql + 4];
    }

    for (int f = 0; f < NF; f++) {
        // ---- issue next field's gather (independent LDGs, hides DRAM) ----
        if (f + 1 < NF) {
            const int fn = f + 1, s = fn & 1;
            int ia = Xis[rA * NF + fn], ib = Xis[rB * NF + fn];
            tv[s][0] = Xvs[rA * NF + fn]; tv[s][1] = Xvs[rB * NF + fn];
            const float2* pa = reinterpret_cast<const float2*>(tables + ((long)fn * NV + ia) * 16);
            const float2* pb = reinterpret_cast<const float2*>(tables + ((long)fn * NV + ib) * 16);
            ta[s][0] = pa[ql]; ta[s][1] = pa[ql + 4];
            ta[s][2] = pb[ql]; ta[s][3] = pb[ql + 4];
        }

        // ---- convert field f: scale by Xv, fp16 hi/lo split, fragment order ----
        const int s = f & 1;
        unsigned ahi[4], alo[4];
        {
            // a0 = rowA k-lo, a1 = rowB k-lo, a2 = rowA k-hi, a3 = rowB k-hi
            float2 src[4] = { ta[s][0], ta[s][2], ta[s][1], ta[s][3] };
            float  scl[4] = { tv[s][0], tv[s][1], tv[s][0], tv[s][1] };
#pragma unroll
            for (int j = 0; j < 4; j++) {
                float x0 = src[j].x * scl[j];
                float x1 = src[j].y * scl[j];
                __half h0 = __float2half_rn(x0);
                __half h1 = __float2half_rn(x1);
                __half2 hh = __halves2half2(h0, h1);
                __half2 ll = __halves2half2(__float2half_rn(x0 - __half2float(h0)),
                                            __float2half_rn(x1 - __half2float(h1)));
                ahi[j] = *reinterpret_cast<unsigned*>(&hh);
                alo[j] = *reinterpret_cast<unsigned*>(&ll);
            }
        }

        // ---- 8 n-blocks x 2 passes; B frags coalesced, L1-hot ----
        const uint2* bp = g_bf + f * 256 + l;
#pragma unroll
        for (int nb = 0; nb < 8; nb++) {
            uint2 b = bp[nb * 32];
            mma_f16(acc[nb], ahi, b.x, b.y);
            mma_f16(acc[nb], alo, b.x, b.y);
        }
    }

    // ---- x = fo + s^2 (fo and s live in the same lane) ----
#pragma unroll
    for (int nb = 0; nb < 4; nb++)
#pragma unroll
        for (int j = 0; j < 4; j++) {
            int row = (j < 2) ? qr : qr + 8;
            int c = nb * 8 + 2 * ql + (j & 1);
            float fo = acc[nb][j], sv = acc[nb + 4][j];
            xb[row * 33 + c] = fmaf(sv, sv, fo);
        }
    __syncwarp();

    // ---- MLP: 2 lanes per row, 16 outputs each ----
    const int rr = l >> 1, hh = l & 1;
    {
        const float* xr = xb + rr * 33;
#pragma unroll
        for (int j = 0; j < 16; j++) {
            int jj = hh * 16 + j;
            float sum = mlp[2048 + jj];
            const float* wrow = mlp + jj * 32;
#pragma unroll
            for (int k = 0; k < 32; k++) sum = fmaf(xr[k], wrow[k], sum);
            yb[rr * 33 + jj] = fmaxf(sum, 0.0f);
        }
    }
    __syncwarp();
    {
        const float* yr = yb + rr * 33;
#pragma unroll
        for (int j = 0; j < 16; j++) {
            int jj = hh * 16 + j;
            float sum = mlp[2080 + jj];
            const float* wrow = mlp + 1024 + jj * 32;
#pragma unroll
            for (int k = 0; k < 32; k++) sum = fmaf(yr[k], wrow[k], sum);
            xb[rr * 33 + jj] = fmaxf(sum, 0.0f);
        }
    }
    __syncwarp();
    if (hh == 0) {
        float sum = mlp[2144];
        const float* zr = xb + rr * 33;
#pragma unroll
        for (int k = 0; k < 32; k++) sum = fmaf(zr[k], mlp[2112 + k], sum);
        out[row0 + rr] = sum;
    }
}

extern "C" void kernel_launch(void* const* d_in, const int* in_sizes, int n_in,
                              void* d_out, int out_size)
{
    const int*   Xi     = (const int*)  d_in[0];
    const float* Xv     = (const float*)d_in[1];
    const float* tables = (const float*)d_in[2];
    const float* W1     = (const float*)d_in[3];
    const float* Wi     = (const float*)d_in[4];
    const float* l1w    = (const float*)d_in[5];
    const float* l1b    = (const float*)d_in[6];
    const float* l2w    = (const float*)d_in[7];
    const float* l2b    = (const float*)d_in[8];
    const float* lw     = (const float*)d_in[9];
    const float* lb     = (const float*)d_in[10];

    prep_bf<<<(NF * 8 * 32 + 255) / 256, 256>>>(W1, Wi);
    pnn_mma<<<GRID, 32>>>(Xi, Xv, tables, l1w, l1b, l2w, l2b, lw, lb, (float*)d_out);
}